// round 14
// baseline (speedup 1.0000x reference)
#include <cuda_runtime.h>
#include <cuda_fp16.h>
#include <cstdint>

#define MTOK 4096      // B*S
#define DMODEL 2048
#define NHEAD 16
#define DHEAD 128
#define BATCH 2
#define SEQ 2048

// ---- scratch (no cudaMalloc allowed) ----
__device__ __half  g_xh[MTOK * DMODEL];        // half(x) [M][K]
__device__ __half  g_wqt[DMODEL * DMODEL];     // W^T [N][K] half
__device__ __half  g_wkt[DMODEL * DMODEL];
__device__ __half  g_wvt[DMODEL * DMODEL];
__device__ __half  g_wft[DMODEL * DMODEL];
__device__ __half  g_q[MTOK * DMODEL];         // [M][N] half
__device__ __half  g_k[MTOK * DMODEL];         // [M][N] half
__device__ __half  g_vt[MTOK * DMODEL];        // V^T per head: [b][h][dh][s]
__device__ __half  g_h1[MTOK * DMODEL];        // half (feeds FF gemm)
__device__ float   g_o[MTOK * DMODEL];         // [B,H,S,DH] contig == buggy flat view
__device__ float   g_h2[MTOK * DMODEL];

extern __shared__ float g_smem[];

// ============================================================
// helpers
// ============================================================
__device__ __forceinline__ void cp_async16(uint32_t saddr, const void* gaddr) {
    asm volatile("cp.async.cg.shared.global [%0], [%1], 16;\n" :: "r"(saddr), "l"(gaddr));
}
__device__ __forceinline__ void cp_commit() {
    asm volatile("cp.async.commit_group;\n");
}
__device__ __forceinline__ uint32_t pack_h2(float a, float b) {
    __half2 h = __floats2half2_rn(a, b);
    return *(uint32_t*)&h;
}
__device__ __forceinline__ void mma_f16(float* c, const uint32_t* a, const uint32_t* b) {
    asm volatile(
        "mma.sync.aligned.m16n8k16.row.col.f32.f16.f16.f32 "
        "{%0,%1,%2,%3}, {%4,%5,%6,%7}, {%8,%9}, {%0,%1,%2,%3};\n"
        : "+f"(c[0]), "+f"(c[1]), "+f"(c[2]), "+f"(c[3])
        : "r"(a[0]), "r"(a[1]), "r"(a[2]), "r"(a[3]), "r"(b[0]), "r"(b[1]));
}
__device__ __forceinline__ void ldsm_x4(uint32_t& r0, uint32_t& r1, uint32_t& r2, uint32_t& r3,
                                        uint32_t addr) {
    asm volatile("ldmatrix.sync.aligned.m8n8.x4.shared.b16 {%0,%1,%2,%3}, [%4];"
                 : "=r"(r0), "=r"(r1), "=r"(r2), "=r"(r3) : "r"(addr));
}

// ============================================================
// pre-pass: x -> half (same layout)
// ============================================================
__global__ void __launch_bounds__(256) cvt_half_kernel(
    const float* __restrict__ in, __half* __restrict__ out)
{
    int i = (blockIdx.x * 256 + threadIdx.x) * 8;
    float4 v0 = *(const float4*)(in + i);
    float4 v1 = *(const float4*)(in + i + 4);
    uint4 o;
    o.x = pack_h2(v0.x, v0.y);
    o.y = pack_h2(v0.z, v0.w);
    o.z = pack_h2(v1.x, v1.y);
    o.w = pack_h2(v1.z, v1.w);
    *(uint4*)((__half*)out + i) = o;
}

// pre-pass: 4 weights W [K][N] fp32 -> W^T [N][K] half, batched via blockIdx.z
struct WPtrs {
    const float* src[4];
    __half* dst[4];
};
__global__ void __launch_bounds__(256) cvt_transpose4_kernel(WPtrs p)
{
    __shared__ __half tile[32][33];
    const float* in = p.src[blockIdx.z];
    __half* out = p.dst[blockIdx.z];
    const int n0 = blockIdx.x * 32;
    const int k0 = blockIdx.y * 32;
    const int tx = threadIdx.x & 31;
    const int ty = threadIdx.x >> 5;   // 0..7
    #pragma unroll
    for (int i = 0; i < 32; i += 8)
        tile[ty + i][tx] = __float2half_rn(in[(size_t)(k0 + ty + i) * DMODEL + n0 + tx]);
    __syncthreads();
    #pragma unroll
    for (int i = 0; i < 32; i += 8)
        out[(size_t)(n0 + ty + i) * DMODEL + k0 + tx] = tile[tx][ty + i];
}

// ============================================================
// FP16 tensor-core GEMM: C[M,N] = A[M,K](half) @ Wt[N,K](half)^T + bias
// block 128x128x64, 8 warps (64x32 warp tiles), 3-stage cp.async, ldmatrix
// out_mode: 0 = fp32 [M][N], 1 = half [M][N], 2 = half V^T per-head
// ============================================================
#define TBM 128
#define TBN 128
#define TBK 64
#define HS 72
#define HTILE (128 * HS)
#define HSTAGE (2 * HTILE)
#define G_SMEM_BYTES (3 * HSTAGE * 2)  // 110592

__global__ void __launch_bounds__(256, 2) gemm_f16_kernel(
    const __half* __restrict__ A, const __half* __restrict__ Wt,
    const float* __restrict__ bias, void* __restrict__ Cout,
    int out_mode)
{
    const int tid = threadIdx.x;
    const int wid = tid >> 5;
    const int lane = tid & 31;
    const int g = lane >> 2;
    const int t = lane & 3;
    const int wr = wid >> 2;
    const int wc = wid & 3;
    const int R = wr * 64;
    const int Cc = wc * 32;
    const int rowBase = blockIdx.y * TBM;
    const int colBase = blockIdx.x * TBN;
    const int K = DMODEL, N = DMODEL;

    const int a_row = lane & 15;
    const int a_c8  = (lane >> 4) << 3;
    const int b_row = ((lane >> 4) << 3) | (lane & 7);
    const int b_c8  = ((lane >> 3) & 1) << 3;

    __half* stage[3] = { (__half*)g_smem, (__half*)g_smem + HSTAGE,
                         (__half*)g_smem + 2 * HSTAGE };

    auto load_stage = [&](int s, int k0) {
        uint32_t as_u = (uint32_t)__cvta_generic_to_shared(stage[s]);
        uint32_t bs_u = (uint32_t)__cvta_generic_to_shared(stage[s] + HTILE);
        #pragma unroll
        for (int i = 0; i < 4; i++) {
            int c = tid + i * 256;
            int r = c >> 3;
            int o = c & 7;
            cp_async16(as_u + (uint32_t)(r * HS + o * 8) * 2,
                       A + (size_t)(rowBase + r) * K + k0 + o * 8);
        }
        #pragma unroll
        for (int i = 0; i < 4; i++) {
            int c = tid + i * 256;
            int n = c >> 3;
            int o = c & 7;
            cp_async16(bs_u + (uint32_t)(n * HS + o * 8) * 2,
                       Wt + (size_t)(colBase + n) * K + k0 + o * 8);
        }
        cp_commit();
    };

    float acc[4][4][4];
    #pragma unroll
    for (int mi = 0; mi < 4; mi++)
        #pragma unroll
        for (int ni = 0; ni < 4; ni++)
            #pragma unroll
            for (int r = 0; r < 4; r++) acc[mi][ni][r] = 0.f;

    const int T = K / TBK;   // 32
    load_stage(0, 0);
    load_stage(1, TBK);

    for (int it = 0; it < T; it++) {
        if (it == T - 1) {
            asm volatile("cp.async.wait_group 0;\n");
        } else {
            asm volatile("cp.async.wait_group 1;\n");
        }
        __syncthreads();
        if (it + 2 < T) load_stage((it + 2) % 3, (it + 2) * TBK);

        const int buf = it % 3;
        uint32_t as_u = (uint32_t)__cvta_generic_to_shared(stage[buf]);
        uint32_t bs_u = (uint32_t)__cvta_generic_to_shared(stage[buf] + HTILE);

        #pragma unroll
        for (int ks = 0; ks < 4; ks++) {
            const int kk = ks * 16;
            uint32_t af[4][4], bf[4][2];
            #pragma unroll
            for (int mi = 0; mi < 4; mi++) {
                uint32_t addr = as_u + 2u * (uint32_t)((R + mi * 16 + a_row) * HS + kk + a_c8);
                ldsm_x4(af[mi][0], af[mi][1], af[mi][2], af[mi][3], addr);
            }
            #pragma unroll
            for (int pr = 0; pr < 2; pr++) {
                uint32_t addr = bs_u + 2u * (uint32_t)((Cc + pr * 16 + b_row) * HS + kk + b_c8);
                ldsm_x4(bf[2 * pr][0], bf[2 * pr][1], bf[2 * pr + 1][0], bf[2 * pr + 1][1], addr);
            }
            #pragma unroll
            for (int mi = 0; mi < 4; mi++)
                #pragma unroll
                for (int ni = 0; ni < 4; ni++)
                    mma_f16(acc[mi][ni], af[mi], bf[ni]);
        }
    }

    #pragma unroll
    for (int mi = 0; mi < 4; mi++) {
        int r0 = rowBase + R + mi * 16 + g;
        #pragma unroll
        for (int ni = 0; ni < 4; ni++) {
            int cb = colBase + Cc + ni * 8 + 2 * t;
            float bx = bias[cb], by = bias[cb + 1];
            float v00 = acc[mi][ni][0] + bx, v01 = acc[mi][ni][1] + by;
            float v10 = acc[mi][ni][2] + bx, v11 = acc[mi][ni][3] + by;
            if (out_mode == 0) {
                float* Cf = (float*)Cout;
                *(float2*)(Cf + (size_t)r0 * N + cb) = make_float2(v00, v01);
                *(float2*)(Cf + (size_t)(r0 + 8) * N + cb) = make_float2(v10, v11);
            } else if (out_mode == 1) {
                __half* Ch = (__half*)Cout;
                *(uint32_t*)(Ch + (size_t)r0 * N + cb) = pack_h2(v00, v01);
                *(uint32_t*)(Ch + (size_t)(r0 + 8) * N + cb) = pack_h2(v10, v11);
            } else {
                __half* Ct = (__half*)Cout;
                int b0 = r0 >> 11, s0 = r0 & 2047;
                int b1 = (r0 + 8) >> 11, s1 = (r0 + 8) & 2047;
                int h = cb >> 7, dh = cb & 127;
                size_t base0 = ((size_t)(b0 * NHEAD + h) * DHEAD + dh) * SEQ;
                size_t base1 = ((size_t)(b1 * NHEAD + h) * DHEAD + dh) * SEQ;
                Ct[base0 + s0] = __float2half_rn(v00);
                Ct[base0 + SEQ + s0] = __float2half_rn(v01);
                Ct[base1 + s1] = __float2half_rn(v10);
                Ct[base1 + SEQ + s1] = __float2half_rn(v11);
            }
        }
    }
}

// ============================================================
// FP16 tensor-core flash attention: BQ=128 (8 warps), BKV=128,
// 3-stage cp.async pipeline, ldmatrix frags, register-resident P,
// exp2-domain online softmax.
// ============================================================
#define FKH 136                      // K tile stride (halfs)
#define FVH 136                      // V^T tile stride (halfs)
#define KVH (128 * FKH + 128 * FVH)  // halfs per stage = 34816
#define FA_SMEM_BYTES (3 * KVH * 2)  // 208896

__global__ void __launch_bounds__(256) flash_attn_f16_kernel(
    const __half* __restrict__ Q, const __half* __restrict__ K,
    const __half* __restrict__ Vt, float* __restrict__ O)
{
    __half* stg[3] = { (__half*)g_smem, (__half*)g_smem + KVH, (__half*)g_smem + 2 * KVH };

    const int tid = threadIdx.x;
    const int w = tid >> 5;           // 0..7
    const int lane = tid & 31;
    const int g = lane >> 2;
    const int t = lane & 3;
    const int q0 = blockIdx.x * 128;
    const int h  = blockIdx.y;
    const int b  = blockIdx.z;
    // exp2 domain: p = exp2(s*c2 - m2),  c2 = (1/sqrt(128))*log2(e)
    const float c2 = 0.12753785366864034f;
    const size_t base = (size_t)b * SEQ * DMODEL + (size_t)h * DHEAD;
    const size_t vbase = (size_t)(b * NHEAD + h) * DHEAD * SEQ;

    const int b_row = ((lane >> 4) << 3) | (lane & 7);
    const int b_c8  = ((lane >> 3) & 1) << 3;

    auto stage_kv = [&](int s, int t0) {
        uint32_t su = (uint32_t)__cvta_generic_to_shared(stg[s]);
        #pragma unroll
        for (int i = 0; i < 8; i++) {
            int c = tid + i * 256;
            int r = c >> 4, o = c & 15;
            cp_async16(su + (uint32_t)(r * FKH + o * 8) * 2,
                       K + base + (size_t)(t0 + r) * DMODEL + o * 8);
        }
        #pragma unroll
        for (int i = 0; i < 8; i++) {
            int c = tid + i * 256;
            int r = c >> 4, o = c & 15;
            cp_async16(su + (uint32_t)(128 * FKH + r * FVH + o * 8) * 2,
                       Vt + vbase + (size_t)r * SEQ + t0 + o * 8);
        }
        cp_commit();
    };

    // Q fragments from global (once)
    uint32_t qa[8][4];
    {
        const __half* Qp0 = Q + base + (size_t)(q0 + w * 16 + g) * DMODEL;
        const __half* Qp1 = Qp0 + (size_t)8 * DMODEL;
        #pragma unroll
        for (int kk = 0; kk < 8; kk++) {
            qa[kk][0] = *(const uint32_t*)&Qp0[kk * 16 + 2 * t];
            qa[kk][1] = *(const uint32_t*)&Qp1[kk * 16 + 2 * t];
            qa[kk][2] = *(const uint32_t*)&Qp0[kk * 16 + 2 * t + 8];
            qa[kk][3] = *(const uint32_t*)&Qp1[kk * 16 + 2 * t + 8];
        }
    }

    float o_acc[16][4];
    #pragma unroll
    for (int ni = 0; ni < 16; ni++)
        #pragma unroll
        for (int r = 0; r < 4; r++) o_acc[ni][r] = 0.f;
    float m0r = -1e30f, m1r = -1e30f, l0r = 0.f, l1r = 0.f;   // m in log2 domain

    const int T = SEQ / 128;   // 16
    stage_kv(0, 0);
    stage_kv(1, 128);

    for (int it = 0; it < T; it++) {
        if (it == T - 1) {
            asm volatile("cp.async.wait_group 0;\n");
        } else {
            asm volatile("cp.async.wait_group 1;\n");
        }
        __syncthreads();
        if (it + 2 < T) stage_kv((it + 2) % 3, (it + 2) * 128);

        const int buf = it % 3;
        const uint32_t ks_u = (uint32_t)__cvta_generic_to_shared(stg[buf]);
        const uint32_t vs_u = ks_u + 128 * FKH * 2;

        // S = Q K^T  (8 k-steps x 16 n-tiles), raw logits
        float s[16][4];
        #pragma unroll
        for (int ni = 0; ni < 16; ni++)
            #pragma unroll
            for (int r = 0; r < 4; r++) s[ni][r] = 0.f;

        #pragma unroll
        for (int kk = 0; kk < 8; kk++) {
            uint32_t kf[16][2];
            #pragma unroll
            for (int pr = 0; pr < 8; pr++) {
                uint32_t addr = ks_u + 2u * (uint32_t)((pr * 16 + b_row) * FKH + kk * 16 + b_c8);
                ldsm_x4(kf[2 * pr][0], kf[2 * pr][1], kf[2 * pr + 1][0], kf[2 * pr + 1][1], addr);
            }
            #pragma unroll
            for (int ni = 0; ni < 16; ni++)
                mma_f16(s[ni], qa[kk], kf[ni]);
        }

        // online softmax in exp2 domain (raw max, then scale once)
        float mt0 = -1e30f, mt1 = -1e30f;
        #pragma unroll
        for (int ni = 0; ni < 16; ni++) {
            mt0 = fmaxf(mt0, fmaxf(s[ni][0], s[ni][1]));
            mt1 = fmaxf(mt1, fmaxf(s[ni][2], s[ni][3]));
        }
        #pragma unroll
        for (int off = 1; off <= 2; off <<= 1) {
            mt0 = fmaxf(mt0, __shfl_xor_sync(0xffffffffu, mt0, off));
            mt1 = fmaxf(mt1, __shfl_xor_sync(0xffffffffu, mt1, off));
        }
        float mn0 = fmaxf(m0r, mt0 * c2), mn1 = fmaxf(m1r, mt1 * c2);
        float c0 = exp2f(m0r - mn0), c1 = exp2f(m1r - mn1);
        float rs0 = 0.f, rs1 = 0.f;
        #pragma unroll
        for (int ni = 0; ni < 16; ni++) {
            s[ni][0] = exp2f(fmaf(s[ni][0], c2, -mn0));
            s[ni][1] = exp2f(fmaf(s[ni][1], c2, -mn0));
            s[ni][2] = exp2f(fmaf(s[ni][2], c2, -mn1));
            s[ni][3] = exp2f(fmaf(s[ni][3], c2, -mn1));
            rs0 += s[ni][0] + s[ni][1];
            rs1 += s[ni][2] + s[ni][3];
        }
        #pragma unroll
        for (int off = 1; off <= 2; off <<= 1) {
            rs0 += __shfl_xor_sync(0xffffffffu, rs0, off);
            rs1 += __shfl_xor_sync(0xffffffffu, rs1, off);
        }
        l0r = l0r * c0 + rs0;  m0r = mn0;
        l1r = l1r * c1 + rs1;  m1r = mn1;
        #pragma unroll
        for (int ni = 0; ni < 16; ni++) {
            o_acc[ni][0] *= c0; o_acc[ni][1] *= c0;
            o_acc[ni][2] *= c1; o_acc[ni][3] *= c1;
        }

        // pack P register->register (C-frag == A-frag layout)
        uint32_t pa[8][4];
        #pragma unroll
        for (int kk = 0; kk < 8; kk++) {
            pa[kk][0] = pack_h2(s[2 * kk][0],     s[2 * kk][1]);
            pa[kk][1] = pack_h2(s[2 * kk][2],     s[2 * kk][3]);
            pa[kk][2] = pack_h2(s[2 * kk + 1][0], s[2 * kk + 1][1]);
            pa[kk][3] = pack_h2(s[2 * kk + 1][2], s[2 * kk + 1][3]);
        }

        // O += P @ V  (8 k-steps of 16 over kv, 16 n-tiles over dh)
        #pragma unroll
        for (int kk = 0; kk < 8; kk++) {
            uint32_t vf[16][2];
            #pragma unroll
            for (int pr = 0; pr < 8; pr++) {
                uint32_t addr = vs_u + 2u * (uint32_t)((pr * 16 + b_row) * FVH + kk * 16 + b_c8);
                ldsm_x4(vf[2 * pr][0], vf[2 * pr][1], vf[2 * pr + 1][0], vf[2 * pr + 1][1], addr);
            }
            #pragma unroll
            for (int ni = 0; ni < 16; ni++)
                mma_f16(o_acc[ni], pa[kk], vf[ni]);
        }
    }

    float inv0 = 1.f / l0r, inv1 = 1.f / l1r;
    size_t ob0 = (((size_t)b * NHEAD + h) * SEQ + (q0 + w * 16 + g)) * DHEAD;
    size_t ob1 = ob0 + (size_t)8 * DHEAD;
    #pragma unroll
    for (int ni = 0; ni < 16; ni++) {
        int cb = ni * 8 + 2 * t;
        *(float2*)(O + ob0 + cb) = make_float2(o_acc[ni][0] * inv0, o_acc[ni][1] * inv0);
        *(float2*)(O + ob1 + cb) = make_float2(o_acc[ni][2] * inv1, o_acc[ni][3] * inv1);
    }
}

// ============================================================
// out = LayerNorm(A + Bb) * gamma + beta   (row = 2048)
// ============================================================
template <bool OUT_HALF>
__global__ void __launch_bounds__(256) add_ln_kernel(
    const float* __restrict__ A, const float* __restrict__ Bb,
    const float* __restrict__ gamma, const float* __restrict__ beta,
    void* __restrict__ outv)
{
    const int row = blockIdx.x;
    const int tid = threadIdx.x;
    const float* a  = A  + (size_t)row * DMODEL;
    const float* bb = Bb + (size_t)row * DMODEL;

    float v[8];
    float s = 0.f, sq = 0.f;
    #pragma unroll
    for (int i = 0; i < 8; i++) {
        int idx = tid + i * 256;
        float x = a[idx] + bb[idx];
        v[i] = x;
        s += x;
        sq += x * x;
    }
    #pragma unroll
    for (int off = 16; off >= 1; off >>= 1) {
        s  += __shfl_xor_sync(0xffffffffu, s, off);
        sq += __shfl_xor_sync(0xffffffffu, sq, off);
    }
    __shared__ float red[2][8];
    __shared__ float fmean, finv;
    int wid = tid >> 5, lane = tid & 31;
    if (lane == 0) { red[0][wid] = s; red[1][wid] = sq; }
    __syncthreads();
    if (tid == 0) {
        float ts = 0.f, tq = 0.f;
        #pragma unroll
        for (int w = 0; w < 8; w++) { ts += red[0][w]; tq += red[1][w]; }
        float mean = ts * (1.f / DMODEL);
        float var = tq * (1.f / DMODEL) - mean * mean;
        fmean = mean;
        finv = rsqrtf(var + 1e-5f);
    }
    __syncthreads();
    float mean = fmean, inv = finv;
    #pragma unroll
    for (int i = 0; i < 8; i++) {
        int idx = tid + i * 256;
        float r = (v[i] - mean) * inv * gamma[idx] + beta[idx];
        if (OUT_HALF) {
            ((__half*)outv)[(size_t)row * DMODEL + idx] = __float2half_rn(r);
        } else {
            ((float*)outv)[(size_t)row * DMODEL + idx] = r;
        }
    }
}

// ============================================================
extern "C" void kernel_launch(void* const* d_in, const int* in_sizes, int n_in,
                              void* d_out, int out_size)
{
    const float* x     = (const float*)d_in[0];
    const float* wq    = (const float*)d_in[1];
    const float* bq    = (const float*)d_in[2];
    const float* wk    = (const float*)d_in[3];
    const float* bk    = (const float*)d_in[4];
    const float* wv    = (const float*)d_in[5];
    const float* bv    = (const float*)d_in[6];
    const float* wf    = (const float*)d_in[7];
    const float* bf    = (const float*)d_in[8];
    const float* gamma = (const float*)d_in[9];
    const float* beta  = (const float*)d_in[10];
    float* out = (float*)d_out;

    __half *xh, *wqt, *wkt, *wvt, *wft, *q, *k, *vt, *h1;
    float *o, *h2;
    cudaGetSymbolAddress((void**)&xh,  g_xh);
    cudaGetSymbolAddress((void**)&wqt, g_wqt);
    cudaGetSymbolAddress((void**)&wkt, g_wkt);
    cudaGetSymbolAddress((void**)&wvt, g_wvt);
    cudaGetSymbolAddress((void**)&wft, g_wft);
    cudaGetSymbolAddress((void**)&q,   g_q);
    cudaGetSymbolAddress((void**)&k,   g_k);
    cudaGetSymbolAddress((void**)&vt,  g_vt);
    cudaGetSymbolAddress((void**)&h1,  g_h1);
    cudaGetSymbolAddress((void**)&o,   g_o);
    cudaGetSymbolAddress((void**)&h2,  g_h2);

    const dim3 gemm_grid(DMODEL / TBN, MTOK / TBM);              // (16, 32)

    static int attr_done = 0;
    if (!attr_done) {
        cudaFuncSetAttribute(gemm_f16_kernel,
                             cudaFuncAttributeMaxDynamicSharedMemorySize,
                             G_SMEM_BYTES);
        cudaFuncSetAttribute(flash_attn_f16_kernel,
                             cudaFuncAttributeMaxDynamicSharedMemorySize,
                             FA_SMEM_BYTES);
        attr_done = 1;
    }

    // pre-pass: x -> half; 4 weights -> transposed half (one batched launch)
    cvt_half_kernel<<<MTOK * DMODEL / 2048, 256>>>(x, xh);
    WPtrs wp;
    wp.src[0] = wq;  wp.dst[0] = wqt;
    wp.src[1] = wk;  wp.dst[1] = wkt;
    wp.src[2] = wv;  wp.dst[2] = wvt;
    wp.src[3] = wf;  wp.dst[3] = wft;
    cvt_transpose4_kernel<<<dim3(DMODEL / 32, DMODEL / 32, 4), 256>>>(wp);

    gemm_f16_kernel<<<gemm_grid, 256, G_SMEM_BYTES>>>(xh, wqt, bq, q, 1);
    gemm_f16_kernel<<<gemm_grid, 256, G_SMEM_BYTES>>>(xh, wkt, bk, k, 1);
    gemm_f16_kernel<<<gemm_grid, 256, G_SMEM_BYTES>>>(xh, wvt, bv, vt, 2);

    flash_attn_f16_kernel<<<dim3(SEQ / 128, NHEAD, BATCH), 256, FA_SMEM_BYTES>>>(q, k, vt, o);

    add_ln_kernel<true><<<MTOK, 256>>>(o, x, gamma, beta, h1);
    gemm_f16_kernel<<<gemm_grid, 256, G_SMEM_BYTES>>>(h1, wft, bf, h2, 0);
    add_ln_kernel<false><<<MTOK, 256>>>(h2, o, gamma, beta, out);
}

// round 16
// speedup vs baseline: 1.0434x; 1.0434x over previous
#include <cuda_runtime.h>
#include <cuda_fp16.h>
#include <cstdint>

#define MTOK 4096      // B*S
#define DMODEL 2048
#define NHEAD 16
#define DHEAD 128
#define BATCH 2
#define SEQ 2048

// ---- scratch (no cudaMalloc allowed) ----
__device__ __half  g_xh[MTOK * DMODEL];        // half(x) [M][K]
__device__ __half  g_wqt[DMODEL * DMODEL];     // W^T [N][K] half
__device__ __half  g_wkt[DMODEL * DMODEL];
__device__ __half  g_wvt[DMODEL * DMODEL];
__device__ __half  g_wft[DMODEL * DMODEL];
__device__ __half  g_q[MTOK * DMODEL];         // [M][N] half
__device__ __half  g_k[MTOK * DMODEL];         // [M][N] half
__device__ __half  g_vt[MTOK * DMODEL];        // V^T per head: [b][h][dh][s]
__device__ __half  g_h1[MTOK * DMODEL];        // half (feeds FF gemm)
__device__ float   g_o[MTOK * DMODEL];         // [B,H,S,DH] contig == buggy flat view
__device__ float   g_h2[MTOK * DMODEL];

extern __shared__ float g_smem[];

// ============================================================
// helpers
// ============================================================
__device__ __forceinline__ void cp_async16(uint32_t saddr, const void* gaddr) {
    asm volatile("cp.async.cg.shared.global [%0], [%1], 16;\n" :: "r"(saddr), "l"(gaddr));
}
__device__ __forceinline__ void cp_commit() {
    asm volatile("cp.async.commit_group;\n");
}
__device__ __forceinline__ uint32_t pack_h2(float a, float b) {
    __half2 h = __floats2half2_rn(a, b);
    return *(uint32_t*)&h;
}
__device__ __forceinline__ void mma_f16(float* c, const uint32_t* a, const uint32_t* b) {
    asm volatile(
        "mma.sync.aligned.m16n8k16.row.col.f32.f16.f16.f32 "
        "{%0,%1,%2,%3}, {%4,%5,%6,%7}, {%8,%9}, {%0,%1,%2,%3};\n"
        : "+f"(c[0]), "+f"(c[1]), "+f"(c[2]), "+f"(c[3])
        : "r"(a[0]), "r"(a[1]), "r"(a[2]), "r"(a[3]), "r"(b[0]), "r"(b[1]));
}
__device__ __forceinline__ void ldsm_x4(uint32_t& r0, uint32_t& r1, uint32_t& r2, uint32_t& r3,
                                        uint32_t addr) {
    asm volatile("ldmatrix.sync.aligned.m8n8.x4.shared.b16 {%0,%1,%2,%3}, [%4];"
                 : "=r"(r0), "=r"(r1), "=r"(r2), "=r"(r3) : "r"(addr));
}

// ============================================================
// pre-pass: x -> half (same layout)
// ============================================================
__global__ void __launch_bounds__(256) cvt_half_kernel(
    const float* __restrict__ in, __half* __restrict__ out)
{
    int i = (blockIdx.x * 256 + threadIdx.x) * 8;
    float4 v0 = *(const float4*)(in + i);
    float4 v1 = *(const float4*)(in + i + 4);
    uint4 o;
    o.x = pack_h2(v0.x, v0.y);
    o.y = pack_h2(v0.z, v0.w);
    o.z = pack_h2(v1.x, v1.y);
    o.w = pack_h2(v1.z, v1.w);
    *(uint4*)((__half*)out + i) = o;
}

// pre-pass: 4 weights W [K][N] fp32 -> W^T [N][K] half, batched via blockIdx.z
struct WPtrs {
    const float* src[4];
    __half* dst[4];
};
__global__ void __launch_bounds__(256) cvt_transpose4_kernel(WPtrs p)
{
    __shared__ __half tile[32][33];
    const float* in = p.src[blockIdx.z];
    __half* out = p.dst[blockIdx.z];
    const int n0 = blockIdx.x * 32;
    const int k0 = blockIdx.y * 32;
    const int tx = threadIdx.x & 31;
    const int ty = threadIdx.x >> 5;   // 0..7
    #pragma unroll
    for (int i = 0; i < 32; i += 8)
        tile[ty + i][tx] = __float2half_rn(in[(size_t)(k0 + ty + i) * DMODEL + n0 + tx]);
    __syncthreads();
    #pragma unroll
    for (int i = 0; i < 32; i += 8)
        out[(size_t)(n0 + ty + i) * DMODEL + k0 + tx] = tile[tx][ty + i];
}

// ============================================================
// FP16 tensor-core GEMM: C[M,N] = A[M,K](half) @ Wt[N,K](half)^T + bias
// block 128x128x64, 8 warps (64x32 warp tiles), 3-stage cp.async, ldmatrix
// Batched over blockIdx.z: per-z weight/bias/out/mode.
// mode: 0 = fp32 [M][N], 1 = half [M][N], 2 = half V^T per-head
// ============================================================
#define TBM 128
#define TBN 128
#define TBK 64
#define HS 72
#define HTILE (128 * HS)
#define HSTAGE (2 * HTILE)
#define G_SMEM_BYTES (3 * HSTAGE * 2)  // 110592

struct GemmBatch {
    const __half* Wt[3];
    const float* bias[3];
    void* C[3];
    int mode[3];
};

__global__ void __launch_bounds__(256, 2) gemm_f16_kernel(
    const __half* __restrict__ A, GemmBatch gb)
{
    const int z = blockIdx.z;
    const __half* __restrict__ Wt = gb.Wt[z];
    const float* __restrict__ bias = gb.bias[z];
    void* __restrict__ Cout = gb.C[z];
    const int out_mode = gb.mode[z];

    const int tid = threadIdx.x;
    const int wid = tid >> 5;
    const int lane = tid & 31;
    const int g = lane >> 2;
    const int t = lane & 3;
    const int wr = wid >> 2;
    const int wc = wid & 3;
    const int R = wr * 64;
    const int Cc = wc * 32;
    const int rowBase = blockIdx.y * TBM;
    const int colBase = blockIdx.x * TBN;
    const int K = DMODEL, N = DMODEL;

    const int a_row = lane & 15;
    const int a_c8  = (lane >> 4) << 3;
    const int b_row = ((lane >> 4) << 3) | (lane & 7);
    const int b_c8  = ((lane >> 3) & 1) << 3;

    __half* stage[3] = { (__half*)g_smem, (__half*)g_smem + HSTAGE,
                         (__half*)g_smem + 2 * HSTAGE };

    auto load_stage = [&](int s, int k0) {
        uint32_t as_u = (uint32_t)__cvta_generic_to_shared(stage[s]);
        uint32_t bs_u = (uint32_t)__cvta_generic_to_shared(stage[s] + HTILE);
        #pragma unroll
        for (int i = 0; i < 4; i++) {
            int c = tid + i * 256;
            int r = c >> 3;
            int o = c & 7;
            cp_async16(as_u + (uint32_t)(r * HS + o * 8) * 2,
                       A + (size_t)(rowBase + r) * K + k0 + o * 8);
        }
        #pragma unroll
        for (int i = 0; i < 4; i++) {
            int c = tid + i * 256;
            int n = c >> 3;
            int o = c & 7;
            cp_async16(bs_u + (uint32_t)(n * HS + o * 8) * 2,
                       Wt + (size_t)(colBase + n) * K + k0 + o * 8);
        }
        cp_commit();
    };

    float acc[4][4][4];
    #pragma unroll
    for (int mi = 0; mi < 4; mi++)
        #pragma unroll
        for (int ni = 0; ni < 4; ni++)
            #pragma unroll
            for (int r = 0; r < 4; r++) acc[mi][ni][r] = 0.f;

    const int T = K / TBK;   // 32
    load_stage(0, 0);
    load_stage(1, TBK);

    for (int it = 0; it < T; it++) {
        if (it == T - 1) {
            asm volatile("cp.async.wait_group 0;\n");
        } else {
            asm volatile("cp.async.wait_group 1;\n");
        }
        __syncthreads();
        if (it + 2 < T) load_stage((it + 2) % 3, (it + 2) * TBK);

        const int buf = it % 3;
        uint32_t as_u = (uint32_t)__cvta_generic_to_shared(stage[buf]);
        uint32_t bs_u = (uint32_t)__cvta_generic_to_shared(stage[buf] + HTILE);

        #pragma unroll
        for (int ks = 0; ks < 4; ks++) {
            const int kk = ks * 16;
            uint32_t af[4][4], bf[4][2];
            #pragma unroll
            for (int mi = 0; mi < 4; mi++) {
                uint32_t addr = as_u + 2u * (uint32_t)((R + mi * 16 + a_row) * HS + kk + a_c8);
                ldsm_x4(af[mi][0], af[mi][1], af[mi][2], af[mi][3], addr);
            }
            #pragma unroll
            for (int pr = 0; pr < 2; pr++) {
                uint32_t addr = bs_u + 2u * (uint32_t)((Cc + pr * 16 + b_row) * HS + kk + b_c8);
                ldsm_x4(bf[2 * pr][0], bf[2 * pr][1], bf[2 * pr + 1][0], bf[2 * pr + 1][1], addr);
            }
            #pragma unroll
            for (int mi = 0; mi < 4; mi++)
                #pragma unroll
                for (int ni = 0; ni < 4; ni++)
                    mma_f16(acc[mi][ni], af[mi], bf[ni]);
        }
    }

    #pragma unroll
    for (int mi = 0; mi < 4; mi++) {
        int r0 = rowBase + R + mi * 16 + g;
        #pragma unroll
        for (int ni = 0; ni < 4; ni++) {
            int cb = colBase + Cc + ni * 8 + 2 * t;
            float bx = bias[cb], by = bias[cb + 1];
            float v00 = acc[mi][ni][0] + bx, v01 = acc[mi][ni][1] + by;
            float v10 = acc[mi][ni][2] + bx, v11 = acc[mi][ni][3] + by;
            if (out_mode == 0) {
                float* Cf = (float*)Cout;
                *(float2*)(Cf + (size_t)r0 * N + cb) = make_float2(v00, v01);
                *(float2*)(Cf + (size_t)(r0 + 8) * N + cb) = make_float2(v10, v11);
            } else if (out_mode == 1) {
                __half* Ch = (__half*)Cout;
                *(uint32_t*)(Ch + (size_t)r0 * N + cb) = pack_h2(v00, v01);
                *(uint32_t*)(Ch + (size_t)(r0 + 8) * N + cb) = pack_h2(v10, v11);
            } else {
                __half* Ct = (__half*)Cout;
                int b0 = r0 >> 11, s0 = r0 & 2047;
                int b1 = (r0 + 8) >> 11, s1 = (r0 + 8) & 2047;
                int h = cb >> 7, dh = cb & 127;
                size_t base0 = ((size_t)(b0 * NHEAD + h) * DHEAD + dh) * SEQ;
                size_t base1 = ((size_t)(b1 * NHEAD + h) * DHEAD + dh) * SEQ;
                Ct[base0 + s0] = __float2half_rn(v00);
                Ct[base0 + SEQ + s0] = __float2half_rn(v01);
                Ct[base1 + s1] = __float2half_rn(v10);
                Ct[base1 + SEQ + s1] = __float2half_rn(v11);
            }
        }
    }
}

// ============================================================
// FP16 tensor-core flash attention: BQ=128 (8 warps), BKV=128,
// double-buffered cp.async, ldmatrix frags, register-resident P.
// ============================================================
#define FKH 136                      // K tile stride (halfs)
#define FVH 136                      // V^T tile stride (halfs)
#define KVH (128 * FKH + 128 * FVH)  // halfs per stage = 34816

__global__ void __launch_bounds__(256) flash_attn_f16_kernel(
    const __half* __restrict__ Q, const __half* __restrict__ K,
    const __half* __restrict__ Vt, float* __restrict__ O)
{
    __half* S0 = (__half*)g_smem;
    __half* S1 = S0 + KVH;

    const int tid = threadIdx.x;
    const int w = tid >> 5;           // 0..7
    const int lane = tid & 31;
    const int g = lane >> 2;
    const int t = lane & 3;
    const int q0 = blockIdx.x * 128;
    const int h  = blockIdx.y;
    const int b  = blockIdx.z;
    const float scale = 0.088388347648318447f;   // 1/sqrt(128)
    const size_t base = (size_t)b * SEQ * DMODEL + (size_t)h * DHEAD;
    const size_t vbase = (size_t)(b * NHEAD + h) * DHEAD * SEQ;

    const int b_row = ((lane >> 4) << 3) | (lane & 7);
    const int b_c8  = ((lane >> 3) & 1) << 3;

    const uint32_t s0_u = (uint32_t)__cvta_generic_to_shared(S0);
    const uint32_t s1_u = (uint32_t)__cvta_generic_to_shared(S1);

    auto stage_kv = [&](uint32_t su, int t0) {
        #pragma unroll
        for (int i = 0; i < 8; i++) {
            int c = tid + i * 256;
            int r = c >> 4, o = c & 15;
            cp_async16(su + (uint32_t)(r * FKH + o * 8) * 2,
                       K + base + (size_t)(t0 + r) * DMODEL + o * 8);
        }
        #pragma unroll
        for (int i = 0; i < 8; i++) {
            int c = tid + i * 256;
            int r = c >> 4, o = c & 15;
            cp_async16(su + (uint32_t)(128 * FKH + r * FVH + o * 8) * 2,
                       Vt + vbase + (size_t)r * SEQ + t0 + o * 8);
        }
        cp_commit();
    };

    // Q fragments from global (once)
    uint32_t qa[8][4];
    {
        const __half* Qp0 = Q + base + (size_t)(q0 + w * 16 + g) * DMODEL;
        const __half* Qp1 = Qp0 + (size_t)8 * DMODEL;
        #pragma unroll
        for (int kk = 0; kk < 8; kk++) {
            qa[kk][0] = *(const uint32_t*)&Qp0[kk * 16 + 2 * t];
            qa[kk][1] = *(const uint32_t*)&Qp1[kk * 16 + 2 * t];
            qa[kk][2] = *(const uint32_t*)&Qp0[kk * 16 + 2 * t + 8];
            qa[kk][3] = *(const uint32_t*)&Qp1[kk * 16 + 2 * t + 8];
        }
    }

    float o_acc[16][4];
    #pragma unroll
    for (int ni = 0; ni < 16; ni++)
        #pragma unroll
        for (int r = 0; r < 4; r++) o_acc[ni][r] = 0.f;
    float m0r = -1e30f, m1r = -1e30f, l0r = 0.f, l1r = 0.f;

    stage_kv(s0_u, 0);
    asm volatile("cp.async.wait_group 0;\n");
    __syncthreads();

    for (int it = 0; it < SEQ / 128; it++) {
        const uint32_t ks_u = (it & 1) ? s1_u : s0_u;
        const uint32_t vs_u = ks_u + 128 * FKH * 2;
        if (it + 1 < SEQ / 128) {
            stage_kv((it & 1) ? s0_u : s1_u, (it + 1) * 128);
        }

        // S = Q K^T  (8 k-steps x 16 n-tiles)
        float s[16][4];
        #pragma unroll
        for (int ni = 0; ni < 16; ni++)
            #pragma unroll
            for (int r = 0; r < 4; r++) s[ni][r] = 0.f;

        #pragma unroll
        for (int kk = 0; kk < 8; kk++) {
            uint32_t kf[16][2];
            #pragma unroll
            for (int pr = 0; pr < 8; pr++) {
                uint32_t addr = ks_u + 2u * (uint32_t)((pr * 16 + b_row) * FKH + kk * 16 + b_c8);
                ldsm_x4(kf[2 * pr][0], kf[2 * pr][1], kf[2 * pr + 1][0], kf[2 * pr + 1][1], addr);
            }
            #pragma unroll
            for (int ni = 0; ni < 16; ni++)
                mma_f16(s[ni], qa[kk], kf[ni]);
        }

        // scale + online softmax
        #pragma unroll
        for (int ni = 0; ni < 16; ni++) {
            s[ni][0] *= scale; s[ni][1] *= scale;
            s[ni][2] *= scale; s[ni][3] *= scale;
        }
        float mt0 = -1e30f, mt1 = -1e30f;
        #pragma unroll
        for (int ni = 0; ni < 16; ni++) {
            mt0 = fmaxf(mt0, fmaxf(s[ni][0], s[ni][1]));
            mt1 = fmaxf(mt1, fmaxf(s[ni][2], s[ni][3]));
        }
        #pragma unroll
        for (int off = 1; off <= 2; off <<= 1) {
            mt0 = fmaxf(mt0, __shfl_xor_sync(0xffffffffu, mt0, off));
            mt1 = fmaxf(mt1, __shfl_xor_sync(0xffffffffu, mt1, off));
        }
        float mn0 = fmaxf(m0r, mt0), mn1 = fmaxf(m1r, mt1);
        float c0 = __expf(m0r - mn0), c1 = __expf(m1r - mn1);
        float rs0 = 0.f, rs1 = 0.f;
        #pragma unroll
        for (int ni = 0; ni < 16; ni++) {
            s[ni][0] = __expf(s[ni][0] - mn0);
            s[ni][1] = __expf(s[ni][1] - mn0);
            s[ni][2] = __expf(s[ni][2] - mn1);
            s[ni][3] = __expf(s[ni][3] - mn1);
            rs0 += s[ni][0] + s[ni][1];
            rs1 += s[ni][2] + s[ni][3];
        }
        #pragma unroll
        for (int off = 1; off <= 2; off <<= 1) {
            rs0 += __shfl_xor_sync(0xffffffffu, rs0, off);
            rs1 += __shfl_xor_sync(0xffffffffu, rs1, off);
        }
        l0r = l0r * c0 + rs0;  m0r = mn0;
        l1r = l1r * c1 + rs1;  m1r = mn1;
        #pragma unroll
        for (int ni = 0; ni < 16; ni++) {
            o_acc[ni][0] *= c0; o_acc[ni][1] *= c0;
            o_acc[ni][2] *= c1; o_acc[ni][3] *= c1;
        }

        // pack P register->register (C-frag == A-frag layout)
        uint32_t pa[8][4];
        #pragma unroll
        for (int kk = 0; kk < 8; kk++) {
            pa[kk][0] = pack_h2(s[2 * kk][0],     s[2 * kk][1]);
            pa[kk][1] = pack_h2(s[2 * kk][2],     s[2 * kk][3]);
            pa[kk][2] = pack_h2(s[2 * kk + 1][0], s[2 * kk + 1][1]);
            pa[kk][3] = pack_h2(s[2 * kk + 1][2], s[2 * kk + 1][3]);
        }

        // O += P @ V  (8 k-steps of 16 over kv, 16 n-tiles over dh)
        #pragma unroll
        for (int kk = 0; kk < 8; kk++) {
            uint32_t vf[16][2];
            #pragma unroll
            for (int pr = 0; pr < 8; pr++) {
                uint32_t addr = vs_u + 2u * (uint32_t)((pr * 16 + b_row) * FVH + kk * 16 + b_c8);
                ldsm_x4(vf[2 * pr][0], vf[2 * pr][1], vf[2 * pr + 1][0], vf[2 * pr + 1][1], addr);
            }
            #pragma unroll
            for (int ni = 0; ni < 16; ni++)
                mma_f16(o_acc[ni], pa[kk], vf[ni]);
        }

        asm volatile("cp.async.wait_group 0;\n");
        __syncthreads();
    }

    float inv0 = 1.f / l0r, inv1 = 1.f / l1r;
    size_t ob0 = (((size_t)b * NHEAD + h) * SEQ + (q0 + w * 16 + g)) * DHEAD;
    size_t ob1 = ob0 + (size_t)8 * DHEAD;
    #pragma unroll
    for (int ni = 0; ni < 16; ni++) {
        int cb = ni * 8 + 2 * t;
        *(float2*)(O + ob0 + cb) = make_float2(o_acc[ni][0] * inv0, o_acc[ni][1] * inv0);
        *(float2*)(O + ob1 + cb) = make_float2(o_acc[ni][2] * inv1, o_acc[ni][3] * inv1);
    }
}

// ============================================================
// out = LayerNorm(A + Bb) * gamma + beta   (row = 2048)
// ============================================================
template <bool OUT_HALF>
__global__ void __launch_bounds__(256) add_ln_kernel(
    const float* __restrict__ A, const float* __restrict__ Bb,
    const float* __restrict__ gamma, const float* __restrict__ beta,
    void* __restrict__ outv)
{
    const int row = blockIdx.x;
    const int tid = threadIdx.x;
    const float* a  = A  + (size_t)row * DMODEL;
    const float* bb = Bb + (size_t)row * DMODEL;

    float v[8];
    float s = 0.f, sq = 0.f;
    #pragma unroll
    for (int i = 0; i < 8; i++) {
        int idx = tid + i * 256;
        float x = a[idx] + bb[idx];
        v[i] = x;
        s += x;
        sq += x * x;
    }
    #pragma unroll
    for (int off = 16; off >= 1; off >>= 1) {
        s  += __shfl_xor_sync(0xffffffffu, s, off);
        sq += __shfl_xor_sync(0xffffffffu, sq, off);
    }
    __shared__ float red[2][8];
    __shared__ float fmean, finv;
    int wid = tid >> 5, lane = tid & 31;
    if (lane == 0) { red[0][wid] = s; red[1][wid] = sq; }
    __syncthreads();
    if (tid == 0) {
        float ts = 0.f, tq = 0.f;
        #pragma unroll
        for (int w = 0; w < 8; w++) { ts += red[0][w]; tq += red[1][w]; }
        float mean = ts * (1.f / DMODEL);
        float var = tq * (1.f / DMODEL) - mean * mean;
        fmean = mean;
        finv = rsqrtf(var + 1e-5f);
    }
    __syncthreads();
    float mean = fmean, inv = finv;
    #pragma unroll
    for (int i = 0; i < 8; i++) {
        int idx = tid + i * 256;
        float r = (v[i] - mean) * inv * gamma[idx] + beta[idx];
        if (OUT_HALF) {
            ((__half*)outv)[(size_t)row * DMODEL + idx] = __float2half_rn(r);
        } else {
            ((float*)outv)[(size_t)row * DMODEL + idx] = r;
        }
    }
}

// ============================================================
extern "C" void kernel_launch(void* const* d_in, const int* in_sizes, int n_in,
                              void* d_out, int out_size)
{
    const float* x     = (const float*)d_in[0];
    const float* wq    = (const float*)d_in[1];
    const float* bq    = (const float*)d_in[2];
    const float* wk    = (const float*)d_in[3];
    const float* bk    = (const float*)d_in[4];
    const float* wv    = (const float*)d_in[5];
    const float* bv    = (const float*)d_in[6];
    const float* wf    = (const float*)d_in[7];
    const float* bf    = (const float*)d_in[8];
    const float* gamma = (const float*)d_in[9];
    const float* beta  = (const float*)d_in[10];
    float* out = (float*)d_out;

    __half *xh, *wqt, *wkt, *wvt, *wft, *q, *k, *vt, *h1;
    float *o, *h2;
    cudaGetSymbolAddress((void**)&xh,  g_xh);
    cudaGetSymbolAddress((void**)&wqt, g_wqt);
    cudaGetSymbolAddress((void**)&wkt, g_wkt);
    cudaGetSymbolAddress((void**)&wvt, g_wvt);
    cudaGetSymbolAddress((void**)&wft, g_wft);
    cudaGetSymbolAddress((void**)&q,   g_q);
    cudaGetSymbolAddress((void**)&k,   g_k);
    cudaGetSymbolAddress((void**)&vt,  g_vt);
    cudaGetSymbolAddress((void**)&h1,  g_h1);
    cudaGetSymbolAddress((void**)&o,   g_o);
    cudaGetSymbolAddress((void**)&h2,  g_h2);

    const size_t fa_bytes = (size_t)(2 * KVH) * sizeof(__half);  // 139264

    static int attr_done = 0;
    if (!attr_done) {
        cudaFuncSetAttribute(gemm_f16_kernel,
                             cudaFuncAttributeMaxDynamicSharedMemorySize,
                             G_SMEM_BYTES);
        cudaFuncSetAttribute(flash_attn_f16_kernel,
                             cudaFuncAttributeMaxDynamicSharedMemorySize,
                             (int)fa_bytes);
        attr_done = 1;
    }

    // pre-pass: x -> half; 4 weights -> transposed half (one batched launch)
    cvt_half_kernel<<<MTOK * DMODEL / 2048, 256>>>(x, xh);
    WPtrs wp;
    wp.src[0] = wq;  wp.dst[0] = wqt;
    wp.src[1] = wk;  wp.dst[1] = wkt;
    wp.src[2] = wv;  wp.dst[2] = wvt;
    wp.src[3] = wf;  wp.dst[3] = wft;
    cvt_transpose4_kernel<<<dim3(DMODEL / 32, DMODEL / 32, 4), 256>>>(wp);

    // fused QKV: one launch, z = {q, k, v}
    GemmBatch gqkv;
    gqkv.Wt[0] = wqt;  gqkv.bias[0] = bq;  gqkv.C[0] = q;   gqkv.mode[0] = 1;
    gqkv.Wt[1] = wkt;  gqkv.bias[1] = bk;  gqkv.C[1] = k;   gqkv.mode[1] = 1;
    gqkv.Wt[2] = wvt;  gqkv.bias[2] = bv;  gqkv.C[2] = vt;  gqkv.mode[2] = 2;
    gemm_f16_kernel<<<dim3(DMODEL / TBN, MTOK / TBM, 3), 256, G_SMEM_BYTES>>>(xh, gqkv);

    flash_attn_f16_kernel<<<dim3(SEQ / 128, NHEAD, BATCH), 256, fa_bytes>>>(q, k, vt, o);

    add_ln_kernel<true><<<MTOK, 256>>>(o, x, gamma, beta, h1);

    GemmBatch gff;
    gff.Wt[0] = wft;  gff.bias[0] = bf;  gff.C[0] = h2;  gff.mode[0] = 0;
    gff.Wt[1] = wft;  gff.bias[1] = bf;  gff.C[1] = h2;  gff.mode[1] = 0;
    gff.Wt[2] = wft;  gff.bias[2] = bf;  gff.C[2] = h2;  gff.mode[2] = 0;
    gemm_f16_kernel<<<dim3(DMODEL / TBN, MTOK / TBM, 1), 256, G_SMEM_BYTES>>>(h1, gff);

    add_ln_kernel<false><<<MTOK, 256>>>(h2, o, gamma, beta, out);
}